// round 16
// baseline (speedup 1.0000x reference)
#include <cuda_runtime.h>
#include <math.h>

#define BATCH 64
#define SEQ   2048
#define DIN   256
#define DOUT  256
#define MTOT  (BATCH * SEQ)

#define NSCAN   32                   // scan CTAs, 2 batch rows each
#define NWORK   116
#define NCTA    (NSCAN + NWORK)      // 148 = one CTA per SM
#define CHUNK   64
#define NCHUNK  (SEQ / CHUNK)        // 32
#define NTILES  (NCHUNK * BATCH * 4) // 8192 64x64 tiles, time-ordered

#define KREG 128                     // register weights (fits dual-chain budget)
#define NGR  (KREG / 4)              // 32 register-weight groups
#define KSM  (DOUT - KREG)           // 128 smem weights
#define NGS  (KSM / 4)               // 32 smem-weight groups
#define WSTRIDE 132                  // 33 float4/col, 33%8==1 -> conflict-free

// smem (floats): WsT [256][132] | hA [2][256] | hB [2][256]
#define OFF_WST 0
#define OFF_HA  (DOUT * WSTRIDE)            // 33792
#define OFF_HB  (OFF_HA + 2 * DOUT)         // 34304
#define SMEM_FLOATS (OFF_HB + 2 * DOUT)     // 34816
#define SMEM_BYTES (SMEM_FLOATS * (int)sizeof(float))   // 139264

__device__ int g_flags[BATCH * NCHUNK];

__global__ void reset_flags_kernel()
{
    int i = blockIdx.x * blockDim.x + threadIdx.x;
    if (i < BATCH * NCHUNK) g_flags[i] = 0;
}

__device__ __forceinline__ int ld_acquire_gpu(const int* p)
{
    int v;
    asm volatile("ld.acquire.gpu.global.b32 %0, [%1];"
                 : "=r"(v) : "l"(p) : "memory");
    return v;
}

// ---------------------------------------------------------------------------
// Bit-exact replica of XLA's EmitFastTanh (Eigen fast tanh, FMA variant).
// ---------------------------------------------------------------------------
__device__ __forceinline__ float xla_tanh(float x)
{
    const float kClamp = 7.99881172180175781f;
    const float kTiny  = 0.0004f;
    const float a1  = 4.89352455891786e-03f;
    const float a3  = 6.37261928875436e-04f;
    const float a5  = 1.48572235717979e-05f;
    const float a7  = 5.12229709037114e-08f;
    const float a9  = -8.60467152213735e-11f;
    const float a11 = 2.00018790482477e-13f;
    const float a13 = -2.76076847742355e-16f;
    const float b0  = 4.89352518554385e-03f;
    const float b2  = 2.26843463243900e-03f;
    const float b4  = 1.18534705686654e-04f;
    const float b6  = 1.19825839466702e-06f;

    float ax = fabsf(x);
    float xc = fminf(fmaxf(x, -kClamp), kClamp);
    float x2 = __fmul_rn(xc, xc);

    float p = __fmaf_rn(x2, a13, a11);
    p = __fmaf_rn(x2, p, a9);
    p = __fmaf_rn(x2, p, a7);
    p = __fmaf_rn(x2, p, a5);
    p = __fmaf_rn(x2, p, a3);
    p = __fmaf_rn(x2, p, a1);
    p = __fmul_rn(xc, p);

    float q = __fmaf_rn(x2, b6, b4);
    q = __fmaf_rn(x2, q, b2);
    q = __fmaf_rn(x2, q, b0);

    float r = __fdiv_rn(p, q);
    return (ax < kTiny) ? x : r;
}

// ---------------------------------------------------------------------------
// GEMM producer: zx = input @ W_x + (b_x+b_h), 64x64 tiles in time order.
// Bit-exact: single fp32 accumulator, ascending k, fused FMA.
// ---------------------------------------------------------------------------
__device__ void gemm_worker(
    float* sm, int worker,
    const float* __restrict__ A,
    const float* __restrict__ W,
    const float* __restrict__ b_h,
    const float* __restrict__ b_x,
    float* __restrict__ C)
{
    float* As   = sm;                // [64][36]
    float* Bs   = sm + 64 * 36;      // [32][64]
    float* bias = sm + 64 * 36 + 32 * 64;

    const int tid = threadIdx.x;
    const int tx = tid & 15;
    const int ty = tid >> 4;

    for (int tau = worker; tau < NTILES; tau += NWORK) {
        const int c  = tau >> 8;
        const int r  = tau & 255;
        const int bb = r >> 2;
        const int nq = r & 3;
        const long m0 = (long)bb * SEQ + (long)c * CHUNK;
        const int n0 = nq * 64;

        if (tid < 64) bias[tid] = __fadd_rn(b_h[n0 + tid], b_x[n0 + tid]);

        float acc[16];
#pragma unroll
        for (int i = 0; i < 16; ++i) acc[i] = 0.f;

        for (int kc = 0; kc < DIN; kc += 32) {
            __syncthreads();
            {
                int i0 = tid, i1 = tid + 256;
                int r0 = i0 >> 3, c0 = (i0 & 7) << 2;
                int r1 = i1 >> 3, c1 = (i1 & 7) << 2;
                float4 v0 = __ldcs((const float4*)(A + (m0 + r0) * DIN + kc + c0));
                float4 v1 = __ldcs((const float4*)(A + (m0 + r1) * DIN + kc + c1));
                As[r0 * 36 + c0 + 0] = v0.x; As[r0 * 36 + c0 + 1] = v0.y;
                As[r0 * 36 + c0 + 2] = v0.z; As[r0 * 36 + c0 + 3] = v0.w;
                As[r1 * 36 + c1 + 0] = v1.x; As[r1 * 36 + c1 + 1] = v1.y;
                As[r1 * 36 + c1 + 2] = v1.z; As[r1 * 36 + c1 + 3] = v1.w;
            }
            {
                int i0 = tid, i1 = tid + 256;
                int k0 = i0 >> 4, g0 = (i0 & 15) << 2;
                int k1 = i1 >> 4, g1 = (i1 & 15) << 2;
                *(float4*)(Bs + k0 * 64 + g0) =
                    *(const float4*)(W + (kc + k0) * DOUT + n0 + g0);
                *(float4*)(Bs + k1 * 64 + g1) =
                    *(const float4*)(W + (kc + k1) * DOUT + n0 + g1);
            }
            __syncthreads();

#pragma unroll
            for (int k = 0; k < 32; ++k) {
                float4 b4 = *(const float4*)(Bs + k * 64 + (tx << 2));
                float a0 = As[(ty * 4 + 0) * 36 + k];
                float a1 = As[(ty * 4 + 1) * 36 + k];
                float a2 = As[(ty * 4 + 2) * 36 + k];
                float a3 = As[(ty * 4 + 3) * 36 + k];
                acc[ 0] = __fmaf_rn(a0, b4.x, acc[ 0]);
                acc[ 1] = __fmaf_rn(a0, b4.y, acc[ 1]);
                acc[ 2] = __fmaf_rn(a0, b4.z, acc[ 2]);
                acc[ 3] = __fmaf_rn(a0, b4.w, acc[ 3]);
                acc[ 4] = __fmaf_rn(a1, b4.x, acc[ 4]);
                acc[ 5] = __fmaf_rn(a1, b4.y, acc[ 5]);
                acc[ 6] = __fmaf_rn(a1, b4.z, acc[ 6]);
                acc[ 7] = __fmaf_rn(a1, b4.w, acc[ 7]);
                acc[ 8] = __fmaf_rn(a2, b4.x, acc[ 8]);
                acc[ 9] = __fmaf_rn(a2, b4.y, acc[ 9]);
                acc[10] = __fmaf_rn(a2, b4.z, acc[10]);
                acc[11] = __fmaf_rn(a2, b4.w, acc[11]);
                acc[12] = __fmaf_rn(a3, b4.x, acc[12]);
                acc[13] = __fmaf_rn(a3, b4.y, acc[13]);
                acc[14] = __fmaf_rn(a3, b4.z, acc[14]);
                acc[15] = __fmaf_rn(a3, b4.w, acc[15]);
            }
        }

#pragma unroll
        for (int i = 0; i < 4; ++i) {
            float4 o;
            o.x = __fadd_rn(acc[i * 4 + 0], bias[(tx << 2) + 0]);
            o.y = __fadd_rn(acc[i * 4 + 1], bias[(tx << 2) + 1]);
            o.z = __fadd_rn(acc[i * 4 + 2], bias[(tx << 2) + 2]);
            o.w = __fadd_rn(acc[i * 4 + 3], bias[(tx << 2) + 3]);
            *(float4*)(C + (m0 + ty * 4 + i) * DOUT + n0 + (tx << 2)) = o;
        }

        __threadfence();
        __syncthreads();
        if (tid == 0) atomicAdd(&g_flags[bb * NCHUNK + c], 1);
    }
}

// ---------------------------------------------------------------------------
// Fused kernel. Scan CTAs [0,32): thread j owns column j of TWO batch rows.
// KREG=128 keeps the dual-chain register budget ~195 (no spill). The two
// independent chains interleave: each hides the other's FMA/LDS latency.
// Weight registers and the smem tail are shared between chains.
// ---------------------------------------------------------------------------
__global__ __launch_bounds__(256, 1) void rnn_fused_kernel(
    const float* __restrict__ input,
    const float* __restrict__ h0,
    const float* __restrict__ Wh,
    const float* __restrict__ Wx,
    const float* __restrict__ b_h,
    const float* __restrict__ b_x,
    float* __restrict__ y,
    float* __restrict__ hfin)
{
    extern __shared__ float sm[];

    if (blockIdx.x >= NSCAN) {
        gemm_worker(sm, blockIdx.x - NSCAN, input, Wx, b_h, b_x, y);
        return;
    }

    float* WsT = sm + OFF_WST;        // [256][WSTRIDE]
    float* hA  = sm + OFF_HA;         // [2][256] batch b0
    float* hB  = sm + OFF_HB;         // [2][256] batch b1

    const int q  = blockIdx.x;
    const int b0 = 2 * q;
    const int b1 = 2 * q + 1;
    const int j  = threadIdx.x;

    float w[KREG];
#pragma unroll
    for (int kk = 0; kk < KREG; ++kk)
        w[kk] = Wh[kk * DOUT + j];

#pragma unroll
    for (int i = 0; i < KSM; ++i)
        WsT[j * WSTRIDE + i] = Wh[(KREG + i) * DOUT + j];

    hA[j] = h0[b0 * DOUT + j];
    hB[j] = h0[b1 * DOUT + j];

    float* ybA = y + (size_t)b0 * SEQ * DOUT;
    float* ybB = y + (size_t)b1 * SEQ * DOUT;
    const float4* wt4 = (const float4*)(WsT + j * WSTRIDE);
    int cur = 0;

    for (int c = 0; c < NCHUNK; ++c) {
        if (j == 0) {
            while (ld_acquire_gpu(&g_flags[b0 * NCHUNK + c]) != 4) { }
        }
        if (j == 32) {   // second warp's lane 0: wait for batch b1 in parallel
            while (ld_acquire_gpu(&g_flags[b1 * NCHUNK + c]) != 4) { }
        }
        __syncthreads();              // chunk gate; also orders setup at c=0

#pragma unroll 1
        for (int ti = 0; ti < CHUNK; ++ti) {
            const size_t t = (size_t)(c * CHUNK + ti) * DOUT + j;

            float zx0 = __ldcs(&ybA[t]);
            float zx1 = __ldcs(&ybB[t]);

            const float4* h4a = (const float4*)(hA + cur * DOUT);
            const float4* h4b = (const float4*)(hB + cur * DOUT);
            float acc0 = 0.f, acc1 = 0.f;

            // k = 0..127: register weights shared by both chains
#pragma unroll
            for (int g = 0; g < NGR; ++g) {
                float4 v0 = h4a[g];
                float4 v1 = h4b[g];
                acc0 = __fmaf_rn(v0.x, w[4 * g + 0], acc0);
                acc1 = __fmaf_rn(v1.x, w[4 * g + 0], acc1);
                acc0 = __fmaf_rn(v0.y, w[4 * g + 1], acc0);
                acc1 = __fmaf_rn(v1.y, w[4 * g + 1], acc1);
                acc0 = __fmaf_rn(v0.z, w[4 * g + 2], acc0);
                acc1 = __fmaf_rn(v1.z, w[4 * g + 2], acc1);
                acc0 = __fmaf_rn(v0.w, w[4 * g + 3], acc0);
                acc1 = __fmaf_rn(v1.w, w[4 * g + 3], acc1);
            }
            // k = 128..255: one smem weight load feeds both chains
#pragma unroll
            for (int g = 0; g < NGS; ++g) {
                float4 wv = wt4[g];
                float4 v0 = h4a[NGR + g];
                float4 v1 = h4b[NGR + g];
                acc0 = __fmaf_rn(v0.x, wv.x, acc0);
                acc1 = __fmaf_rn(v1.x, wv.x, acc1);
                acc0 = __fmaf_rn(v0.y, wv.y, acc0);
                acc1 = __fmaf_rn(v1.y, wv.y, acc1);
                acc0 = __fmaf_rn(v0.z, wv.z, acc0);
                acc1 = __fmaf_rn(v1.z, wv.z, acc1);
                acc0 = __fmaf_rn(v0.w, wv.w, acc0);
                acc1 = __fmaf_rn(v1.w, wv.w, acc1);
            }

            float o0 = xla_tanh(__fadd_rn(acc0, zx0));
            float o1 = xla_tanh(__fadd_rn(acc1, zx1));
            hA[(cur ^ 1) * DOUT + j] = o0;
            hB[(cur ^ 1) * DOUT + j] = o1;
            __stcs(&ybA[t], o0);
            __stcs(&ybB[t], o1);
            __syncthreads();
            cur ^= 1;
        }
    }

    hfin[b0 * DOUT + j] = hA[cur * DOUT + j];
    hfin[b1 * DOUT + j] = hB[cur * DOUT + j];
}

// ---------------------------------------------------------------------------
extern "C" void kernel_launch(void* const* d_in, const int* in_sizes, int n_in,
                              void* d_out, int out_size)
{
    const float* input = (const float*)d_in[0];
    const float* h0    = (const float*)d_in[1];
    const float* W_h   = (const float*)d_in[2];
    const float* W_x   = (const float*)d_in[3];
    const float* b_h   = (const float*)d_in[4];
    const float* b_x   = (const float*)d_in[5];

    float* y    = (float*)d_out;
    float* hfin = y + (size_t)BATCH * SEQ * DOUT;

    cudaFuncSetAttribute(rnn_fused_kernel,
                         cudaFuncAttributeMaxDynamicSharedMemorySize,
                         SMEM_BYTES);

    reset_flags_kernel<<<8, 256>>>();
    rnn_fused_kernel<<<NCTA, 256, SMEM_BYTES>>>(
        input, h0, W_h, W_x, b_h, b_x, y, hfin);
}

// round 17
// speedup vs baseline: 1.8125x; 1.8125x over previous
#include <cuda_runtime.h>
#include <math.h>

#define BATCH 64
#define SEQ   2048
#define DIN   256
#define DOUT  256
#define MTOT  (BATCH * SEQ)

#define NSCAN   64
#define NWORK   84
#define NCTA    (NSCAN + NWORK)      // 148 CTAs = one per SM
#define CHUNK   64
#define NCHUNK  (SEQ / CHUNK)        // 32
#define NTILES  (NCHUNK * BATCH * 4) // 8192 64x64 tiles, time-ordered

#define KREG 192
#define KSM  (DOUT - KREG)           // 64
#define WSTRIDE 68                   // 17 float4/col: conflict-free
#define SCAN_SMEM_FLOATS (DOUT * WSTRIDE + 2 * DOUT)
#define SMEM_BYTES (SCAN_SMEM_FLOATS * (int)sizeof(float))   // 71680

__device__ int g_flags[BATCH * NCHUNK];

__global__ void reset_flags_kernel()
{
    int i = blockIdx.x * blockDim.x + threadIdx.x;
    if (i < BATCH * NCHUNK) g_flags[i] = 0;
}

__device__ __forceinline__ int ld_acquire_gpu(const int* p)
{
    int v;
    asm volatile("ld.acquire.gpu.global.b32 %0, [%1];"
                 : "=r"(v) : "l"(p) : "memory");
    return v;
}

// ---------------------------------------------------------------------------
// Bit-exact replica of XLA's EmitFastTanh (Eigen fast tanh, FMA variant).
// ---------------------------------------------------------------------------
__device__ __forceinline__ float xla_tanh(float x)
{
    const float kClamp = 7.99881172180175781f;
    const float kTiny  = 0.0004f;
    const float a1  = 4.89352455891786e-03f;
    const float a3  = 6.37261928875436e-04f;
    const float a5  = 1.48572235717979e-05f;
    const float a7  = 5.12229709037114e-08f;
    const float a9  = -8.60467152213735e-11f;
    const float a11 = 2.00018790482477e-13f;
    const float a13 = -2.76076847742355e-16f;
    const float b0  = 4.89352518554385e-03f;
    const float b2  = 2.26843463243900e-03f;
    const float b4  = 1.18534705686654e-04f;
    const float b6  = 1.19825839466702e-06f;

    float ax = fabsf(x);
    float xc = fminf(fmaxf(x, -kClamp), kClamp);
    float x2 = __fmul_rn(xc, xc);

    float p = __fmaf_rn(x2, a13, a11);
    p = __fmaf_rn(x2, p, a9);
    p = __fmaf_rn(x2, p, a7);
    p = __fmaf_rn(x2, p, a5);
    p = __fmaf_rn(x2, p, a3);
    p = __fmaf_rn(x2, p, a1);
    p = __fmul_rn(xc, p);

    float q = __fmaf_rn(x2, b6, b4);
    q = __fmaf_rn(x2, q, b2);
    q = __fmaf_rn(x2, q, b0);

    float r = __fdiv_rn(p, q);
    return (ax < kTiny) ? x : r;
}

// ---------------------------------------------------------------------------
// GEMM producer: zx = input @ W_x + (b_x+b_h), 64x64 tiles in time order.
// zx stores use DEFAULT cache policy (consumer reads them a few chunks later).
// Bit-exact: single fp32 accumulator, ascending k, fused FMA.
// ---------------------------------------------------------------------------
__device__ void gemm_worker(
    float* sm, int worker,
    const float* __restrict__ A,
    const float* __restrict__ W,
    const float* __restrict__ b_h,
    const float* __restrict__ b_x,
    float* __restrict__ C)
{
    float* As   = sm;                // [64][36]
    float* Bs   = sm + 64 * 36;      // [32][64]
    float* bias = sm + 64 * 36 + 32 * 64;

    const int tid = threadIdx.x;
    const int tx = tid & 15;
    const int ty = tid >> 4;

    for (int tau = worker; tau < NTILES; tau += NWORK) {
        const int c  = tau >> 8;
        const int r  = tau & 255;
        const int bb = r >> 2;
        const int nq = r & 3;
        const long m0 = (long)bb * SEQ + (long)c * CHUNK;
        const int n0 = nq * 64;

        if (tid < 64) bias[tid] = __fadd_rn(b_h[n0 + tid], b_x[n0 + tid]);

        float acc[16];
#pragma unroll
        for (int i = 0; i < 16; ++i) acc[i] = 0.f;

        for (int kc = 0; kc < DIN; kc += 32) {
            __syncthreads();
            {
                int i0 = tid, i1 = tid + 256;
                int r0 = i0 >> 3, c0 = (i0 & 7) << 2;
                int r1 = i1 >> 3, c1 = (i1 & 7) << 2;
                float4 v0 = __ldcs((const float4*)(A + (m0 + r0) * DIN + kc + c0));
                float4 v1 = __ldcs((const float4*)(A + (m0 + r1) * DIN + kc + c1));
                As[r0 * 36 + c0 + 0] = v0.x; As[r0 * 36 + c0 + 1] = v0.y;
                As[r0 * 36 + c0 + 2] = v0.z; As[r0 * 36 + c0 + 3] = v0.w;
                As[r1 * 36 + c1 + 0] = v1.x; As[r1 * 36 + c1 + 1] = v1.y;
                As[r1 * 36 + c1 + 2] = v1.z; As[r1 * 36 + c1 + 3] = v1.w;
            }
            {
                int i0 = tid, i1 = tid + 256;
                int k0 = i0 >> 4, g0 = (i0 & 15) << 2;
                int k1 = i1 >> 4, g1 = (i1 & 15) << 2;
                *(float4*)(Bs + k0 * 64 + g0) =
                    *(const float4*)(W + (kc + k0) * DOUT + n0 + g0);
                *(float4*)(Bs + k1 * 64 + g1) =
                    *(const float4*)(W + (kc + k1) * DOUT + n0 + g1);
            }
            __syncthreads();

#pragma unroll
            for (int k = 0; k < 32; ++k) {
                float4 b4 = *(const float4*)(Bs + k * 64 + (tx << 2));
                float a0 = As[(ty * 4 + 0) * 36 + k];
                float a1 = As[(ty * 4 + 1) * 36 + k];
                float a2 = As[(ty * 4 + 2) * 36 + k];
                float a3 = As[(ty * 4 + 3) * 36 + k];
                acc[ 0] = __fmaf_rn(a0, b4.x, acc[ 0]);
                acc[ 1] = __fmaf_rn(a0, b4.y, acc[ 1]);
                acc[ 2] = __fmaf_rn(a0, b4.z, acc[ 2]);
                acc[ 3] = __fmaf_rn(a0, b4.w, acc[ 3]);
                acc[ 4] = __fmaf_rn(a1, b4.x, acc[ 4]);
                acc[ 5] = __fmaf_rn(a1, b4.y, acc[ 5]);
                acc[ 6] = __fmaf_rn(a1, b4.z, acc[ 6]);
                acc[ 7] = __fmaf_rn(a1, b4.w, acc[ 7]);
                acc[ 8] = __fmaf_rn(a2, b4.x, acc[ 8]);
                acc[ 9] = __fmaf_rn(a2, b4.y, acc[ 9]);
                acc[10] = __fmaf_rn(a2, b4.z, acc[10]);
                acc[11] = __fmaf_rn(a2, b4.w, acc[11]);
                acc[12] = __fmaf_rn(a3, b4.x, acc[12]);
                acc[13] = __fmaf_rn(a3, b4.y, acc[13]);
                acc[14] = __fmaf_rn(a3, b4.z, acc[14]);
                acc[15] = __fmaf_rn(a3, b4.w, acc[15]);
            }
        }

#pragma unroll
        for (int i = 0; i < 4; ++i) {
            float4 o;
            o.x = __fadd_rn(acc[i * 4 + 0], bias[(tx << 2) + 0]);
            o.y = __fadd_rn(acc[i * 4 + 1], bias[(tx << 2) + 1]);
            o.z = __fadd_rn(acc[i * 4 + 2], bias[(tx << 2) + 2]);
            o.w = __fadd_rn(acc[i * 4 + 3], bias[(tx << 2) + 3]);
            *(float4*)(C + (m0 + ty * 4 + i) * DOUT + n0 + (tx << 2)) = o;
        }

        __threadfence();
        __syncthreads();
        if (tid == 0) atomicAdd(&g_flags[bb * NCHUNK + c], 1);
    }
}

// ---------------------------------------------------------------------------
// One scan step: strict single-accumulator ascending-k FMA chain + XLA tanh.
// ---------------------------------------------------------------------------
__device__ __forceinline__ float scan_step(
    const float4* __restrict__ h4,
    const float* __restrict__ w,
    const float4* __restrict__ wt4,
    float zx)
{
    float acc = 0.f;
#pragma unroll
    for (int g = 0; g < KREG / 4; ++g) {
        float4 hv = h4[g];
        acc = __fmaf_rn(hv.x, w[4 * g + 0], acc);
        acc = __fmaf_rn(hv.y, w[4 * g + 1], acc);
        acc = __fmaf_rn(hv.z, w[4 * g + 2], acc);
        acc = __fmaf_rn(hv.w, w[4 * g + 3], acc);
    }
#pragma unroll
    for (int g = 0; g < KSM / 4; ++g) {
        float4 hv = h4[(KREG >> 2) + g];
        float4 wv = wt4[g];
        acc = __fmaf_rn(hv.x, wv.x, acc);
        acc = __fmaf_rn(hv.y, wv.y, acc);
        acc = __fmaf_rn(hv.z, wv.z, acc);
        acc = __fmaf_rn(hv.w, wv.w, acc);
    }
    return xla_tanh(__fadd_rn(acc, zx));
}

// ---------------------------------------------------------------------------
// Fused kernel. Scan CTAs [0,64): thread j owns column j; step loop unrolled
// by 2 with explicit ping/pong buffers; both zx loads hoisted to pair start.
// ---------------------------------------------------------------------------
__global__ __launch_bounds__(256, 1) void rnn_fused_kernel(
    const float* __restrict__ input,
    const float* __restrict__ h0,
    const float* __restrict__ Wh,
    const float* __restrict__ Wx,
    const float* __restrict__ b_h,
    const float* __restrict__ b_x,
    float* __restrict__ y,
    float* __restrict__ hfin)
{
    extern __shared__ float sm[];

    if (blockIdx.x >= NSCAN) {
        gemm_worker(sm, blockIdx.x - NSCAN, input, Wx, b_h, b_x, y);
        return;
    }

    float* WsT  = sm;                     // [DOUT][WSTRIDE]
    float* hb0  = sm + DOUT * WSTRIDE;    // buffer 0
    float* hb1  = hb0 + DOUT;             // buffer 1

    const int b = blockIdx.x;
    const int j = threadIdx.x;

    float w[KREG];
#pragma unroll
    for (int kk = 0; kk < KREG; ++kk)
        w[kk] = Wh[kk * DOUT + j];

#pragma unroll
    for (int i = 0; i < KSM; ++i)
        WsT[j * WSTRIDE + i] = Wh[(KREG + i) * DOUT + j];

    hb0[j] = h0[b * DOUT + j];

    float* yb = y + (size_t)b * SEQ * DOUT;
    const float4* wt4 = (const float4*)(WsT + j * WSTRIDE);
    const float4* h40 = (const float4*)hb0;
    const float4* h41 = (const float4*)hb1;

    for (int c = 0; c < NCHUNK; ++c) {
        if (j == 0) {
            while (ld_acquire_gpu(&g_flags[b * NCHUNK + c]) != 4) { }
        }
        __syncthreads();                  // chunk gate; also orders setup at c=0

#pragma unroll 1
        for (int ti = 0; ti < CHUNK; ti += 2) {
            const size_t t0 = (size_t)(c * CHUNK + ti) * DOUT + j;

            // both zx loads issued up front: zx1 gets ~2 chains of cover
            float zx0 = __ldcs(&yb[t0]);
            float zx1 = __ldcs(&yb[t0 + DOUT]);

            // step even: hb0 -> hb1
            float v0 = scan_step(h40, w, wt4, zx0);
            hb1[j] = v0;
            __stcs(&yb[t0], v0);
            __syncthreads();

            // step odd: hb1 -> hb0
            float v1 = scan_step(h41, w, wt4, zx1);
            hb0[j] = v1;
            __stcs(&yb[t0 + DOUT], v1);
            __syncthreads();
        }
    }

    hfin[b * DOUT + j] = hb0[j];          // SEQ even: final state in hb0
}

// ---------------------------------------------------------------------------
extern "C" void kernel_launch(void* const* d_in, const int* in_sizes, int n_in,
                              void* d_out, int out_size)
{
    const float* input = (const float*)d_in[0];
    const float* h0    = (const float*)d_in[1];
    const float* W_h   = (const float*)d_in[2];
    const float* W_x   = (const float*)d_in[3];
    const float* b_h   = (const float*)d_in[4];
    const float* b_x   = (const float*)d_in[5];

    float* y    = (float*)d_out;
    float* hfin = y + (size_t)BATCH * SEQ * DOUT;

    cudaFuncSetAttribute(rnn_fused_kernel,
                         cudaFuncAttributeMaxDynamicSharedMemorySize,
                         SMEM_BYTES);

    reset_flags_kernel<<<8, 256>>>();
    rnn_fused_kernel<<<NCTA, 256, SMEM_BYTES>>>(
        input, h0, W_h, W_x, b_h, b_x, y, hfin);
}